// round 13
// baseline (speedup 1.0000x reference)
#include <cuda_runtime.h>
#include <cstdint>

#define BB 1024
#define SS 512
#define DD 64
#define NT 512
#define NCTA 148
#define HALF_BYTES 65536u
#define HALF_FLOATS 16384
#define SM_RED4A 196608              // 4 KB mean partials
#define SM_RED4B (SM_RED4A + 4096)   // 4 KB out partials (e-weighted)
#define SM_EXP   (SM_RED4B + 4096)   // 64 B per-warp exp sums
#define SM_MBAR  (SM_EXP + 64)       // 3 x 8B mbarriers
#define SMEM_TOTAL (SM_MBAR + 64)

__device__ __forceinline__ float2 add2(float2 a, float2 b) {
    float2 d;
    asm("{.reg .b64 ra,rb,rd;\n\t"
        "mov.b64 ra,{%2,%3}; mov.b64 rb,{%4,%5};\n\t"
        "add.rn.f32x2 rd,ra,rb; mov.b64 {%0,%1},rd;}"
        : "=f"(d.x), "=f"(d.y) : "f"(a.x), "f"(a.y), "f"(b.x), "f"(b.y));
    return d;
}
__device__ __forceinline__ float2 fma2(float2 a, float2 b, float2 c) {
    float2 d;
    asm("{.reg .b64 ra,rb,rc,rd;\n\t"
        "mov.b64 ra,{%2,%3}; mov.b64 rb,{%4,%5}; mov.b64 rc,{%6,%7};\n\t"
        "fma.rn.f32x2 rd,ra,rb,rc; mov.b64 {%0,%1},rd;}"
        : "=f"(d.x), "=f"(d.y)
        : "f"(a.x), "f"(a.y), "f"(b.x), "f"(b.y), "f"(c.x), "f"(c.y));
    return d;
}
__device__ __forceinline__ float2 mul2(float2 a, float2 b) {
    float2 d;
    asm("{.reg .b64 ra,rb,rd;\n\t"
        "mov.b64 ra,{%2,%3}; mov.b64 rb,{%4,%5};\n\t"
        "mul.rn.f32x2 rd,ra,rb; mov.b64 {%0,%1},rd;}"
        : "=f"(d.x), "=f"(d.y) : "f"(a.x), "f"(a.y), "f"(b.x), "f"(b.y));
    return d;
}

__device__ __forceinline__ void mbar_wait(uint32_t mbar, uint32_t parity) {
    uint32_t done;
    asm volatile(
        "{\n\t.reg .pred p;\n\t"
        "mbarrier.try_wait.parity.acquire.cta.shared::cta.b64 p, [%1], %2;\n\t"
        "selp.b32 %0, 1, 0, p;\n\t}"
        : "=r"(done) : "r"(mbar), "r"(parity) : "memory");
    while (!done) {
        asm volatile(
            "{\n\t.reg .pred p;\n\t"
            "mbarrier.try_wait.parity.acquire.cta.shared::cta.b64 p, [%1], %2, 0x989680;\n\t"
            "selp.b32 %0, 1, 0, p;\n\t}"
            : "=r"(done) : "r"(mbar), "r"(parity) : "memory");
    }
}

// Issue load of global half h into ring slot h%3. b(h) = b0 + (h>>1)*NCTA.
__device__ __forceinline__ void issue_half(uint32_t base_sa, uint32_t mbar_base_sa,
                                           const float* __restrict__ x, int b0, uint32_t h) {
    const uint32_t slot = h % 3u;
    const uint32_t mbar = mbar_base_sa + slot * 8u;
    const uint32_t dst  = base_sa + slot * HALF_BYTES;
    const int b = b0 + (int)(h >> 1) * NCTA;
    const char* src = (const char*)(x + (size_t)b * (SS * DD) + (h & 1u) * HALF_FLOATS);
    asm volatile("mbarrier.arrive.expect_tx.shared.b64 _, [%0], %1;"
                 :: "r"(mbar), "r"(HALF_BYTES) : "memory");
    asm volatile("cp.async.bulk.shared::cta.global.mbarrier::complete_tx::bytes [%0], [%1], %2, [%3];"
                 :: "r"(dst), "l"(src), "r"(HALF_BYTES), "r"(mbar) : "memory");
}

__global__ __launch_bounds__(NT, 1)
void attnsum_kernel(const float* __restrict__ x,
                    const int* __restrict__ mask,
                    float* __restrict__ out,    // [B, D]
                    float* __restrict__ wout)   // [B, S]
{
    extern __shared__ __align__(16) char smem[];
    float4* red4a = (float4*)(smem + SM_RED4A);
    float4* red4b = (float4*)(smem + SM_RED4B);
    float*  redE  = (float*)(smem + SM_EXP);

    const int t    = threadIdx.x;
    const int lane = t & 31;
    const int wp   = t >> 5;
    const int c    = t & 15;      // owned d-group: d = 4c..4c+3
    const int g    = t >> 4;      // row base: rows s = g + 32*i
    const int r    = g + 32 * c;  // row this thread owns after reduce-scatter

    const uint32_t base_sa = (uint32_t)__cvta_generic_to_shared(smem);
    const uint32_t mbar_sa = (uint32_t)__cvta_generic_to_shared(smem + SM_MBAR);

    if (t < 3)
        asm volatile("mbarrier.init.shared::cta.b64 [%0], 1;"
                     :: "r"(mbar_sa + t * 8u) : "memory");
    __syncthreads();

    const int b0 = blockIdx.x;
    // nb computed arithmetically so TMA can start IMMEDIATELY
    const uint32_t nb = (uint32_t)((BB - 1 - b0) / NCTA) + 1u;
    const uint32_t totalH = 2u * nb;

    if (t == 0) {
        issue_half(base_sa, mbar_sa, x, b0, 0);
        issue_half(base_sa, mbar_sa, x, b0, 1);
        if (2 < totalH) issue_half(base_sa, mbar_sa, x, b0, 2);
    }

    // mask bitmap gather AFTER the first tile loads are in flight — the
    // scattered DRAM reads hide under the ~2.8us first-tile TMA latency.
    uint32_t mkbits = 0;
    {
        uint32_t jj = 0;
        for (int b = b0; b < BB; b += NCTA, ++jj)
            mkbits |= (uint32_t)(mask[b * SS + r] & 1) << jj;
    }

    float e_prev = 0.0f;   // this thread's unnormalized exp for row r, prev batch
    uint32_t h = 0;
    int j = 0;
    for (int b = b0; b < BB; b += NCTA, h += 2, ++j) {
        // ---- consume two halves into registers; mean partials on half0 ----
        float4 v[16];
        float2 p01 = make_float2(0.f, 0.f), p23 = make_float2(0.f, 0.f);
        {
            const uint32_t s0 = h % 3u, pr0 = (h / 3u) & 1u;
            mbar_wait(mbar_sa + s0 * 8u, pr0);
            const float4* half0 = (const float4*)(smem + s0 * HALF_BYTES);
#pragma unroll
            for (int i = 0; i < 8; ++i) v[i] = half0[t + NT * i];
#pragma unroll
            for (int i = 0; i < 8; ++i) {
                p01 = add2(p01, make_float2(v[i].x, v[i].y));
                p23 = add2(p23, make_float2(v[i].z, v[i].w));
            }
            const uint32_t h1 = h + 1;
            const uint32_t s1 = h1 % 3u, pr1 = (h1 / 3u) & 1u;
            mbar_wait(mbar_sa + s1 * 8u, pr1);
            const float4* half1 = (const float4*)(smem + s1 * HALF_BYTES);
#pragma unroll
            for (int i = 0; i < 8; ++i) v[8 + i] = half1[t + NT * i];
        }
        __syncthreads();   // sync 0: tile slots free; prev redE/red4b stable
        if (t == 0) {
            if (h + 3 < totalH) issue_half(base_sa, mbar_sa, x, b0, h + 3);
            if (h + 4 < totalH) issue_half(base_sa, mbar_sa, x, b0, h + 4);
        }

        // ---- lazy normalize + store PREV batch's weights ----
        if (j > 0) {
            float tot = 0.0f;
#pragma unroll
            for (int k = 0; k < 16; ++k) tot += redE[k];
            const float sc = (tot > 0.0f) ? (1.0f / tot) : 0.0f;
            wout[(b - NCTA) * SS + r] = e_prev * sc;
        }

        // ---- mean partials (packed) ----
#pragma unroll
        for (int i = 8; i < 16; ++i) {
            p01 = add2(p01, make_float2(v[i].x, v[i].y));
            p23 = add2(p23, make_float2(v[i].z, v[i].w));
        }
        p01.x += __shfl_xor_sync(0xffffffffu, p01.x, 16);
        p01.y += __shfl_xor_sync(0xffffffffu, p01.y, 16);
        p23.x += __shfl_xor_sync(0xffffffffu, p23.x, 16);
        p23.y += __shfl_xor_sync(0xffffffffu, p23.y, 16);
        if (lane < 16)
            red4a[wp * 16 + lane] = make_float4(p01.x, p01.y, p23.x, p23.y);
        __syncthreads();   // sync 1

        // ---- t<16 window: finalize mean AND finalize+normalize prev out ----
        if (t < 16) {
            float4 m = red4a[t];
#pragma unroll
            for (int k = 1; k < 16; ++k) {
                float4 o = red4a[t + 16 * k];
                float2 a01 = add2(make_float2(m.x, m.y), make_float2(o.x, o.y));
                float2 a23 = add2(make_float2(m.z, m.w), make_float2(o.z, o.w));
                m = make_float4(a01.x, a01.y, a23.x, a23.y);
            }
            red4a[t] = m;
            if (j > 0) {
                float tot = 0.0f;
#pragma unroll
                for (int k = 0; k < 16; ++k) tot += redE[k];
                const float sc = (tot > 0.0f) ? (1.0f / tot) : 0.0f;
                float4 po = red4b[t];
#pragma unroll
                for (int k = 1; k < 16; ++k) {
                    float4 o = red4b[t + 16 * k];
                    float2 a01 = add2(make_float2(po.x, po.y), make_float2(o.x, o.y));
                    float2 a23 = add2(make_float2(po.z, po.w), make_float2(o.z, o.w));
                    po = make_float4(a01.x, a01.y, a23.x, a23.y);
                }
                po.x *= sc; po.y *= sc; po.z *= sc; po.w *= sc;
                ((float4*)out)[(b - NCTA) * 16 + t] = po;
            }
        }
        __syncthreads();   // sync 2
        float4 mean4 = red4a[c];
        const float invS = 1.0f / (float)SS;
        const float2 m01 = make_float2(mean4.x * invS, mean4.y * invS);
        const float2 m23 = make_float2(mean4.z * invS, mean4.w * invS);

        // ---- attn partials (packed dot4) ----
        float a[16];
#pragma unroll
        for (int i = 0; i < 16; ++i) {
            float2 p = mul2(make_float2(v[i].x, v[i].y), m01);
            p = fma2(make_float2(v[i].z, v[i].w), m23, p);
            a[i] = p.x + p.y;
        }
        // ---- log2 reduce-scatter over 16 c-lanes (15 shfls); lane c ends
        //      holding full attn for row r = g + 32*c ----
#pragma unroll
        for (int jj = 0; jj < 8; ++jj) {
            float send = (c & 8) ? a[jj] : a[jj + 8];
            float recv = __shfl_xor_sync(0xffffffffu, send, 8);
            a[jj] = ((c & 8) ? a[jj + 8] : a[jj]) + recv;
        }
#pragma unroll
        for (int jj = 0; jj < 4; ++jj) {
            float send = (c & 4) ? a[jj] : a[jj + 4];
            float recv = __shfl_xor_sync(0xffffffffu, send, 4);
            a[jj] = ((c & 4) ? a[jj + 4] : a[jj]) + recv;
        }
#pragma unroll
        for (int jj = 0; jj < 2; ++jj) {
            float send = (c & 2) ? a[jj] : a[jj + 2];
            float recv = __shfl_xor_sync(0xffffffffu, send, 2);
            a[jj] = ((c & 2) ? a[jj + 2] : a[jj]) + recv;
        }
        {
            float send = (c & 1) ? a[0] : a[1];
            float recv = __shfl_xor_sync(0xffffffffu, send, 1);
            a[0] = ((c & 1) ? a[1] : a[0]) + recv;
        }

        // ---- unnormalized exp (mask bit from register); per-warp sum ----
        const float e = ((mkbits >> j) & 1u) ? __expf(a[0]) : 0.0f;
        float se = e;
        se += __shfl_xor_sync(0xffffffffu, se, 16);
        se += __shfl_xor_sync(0xffffffffu, se, 8);
        se += __shfl_xor_sync(0xffffffffu, se, 4);
        se += __shfl_xor_sync(0xffffffffu, se, 2);
        se += __shfl_xor_sync(0xffffffffu, se, 1);
        if (lane == 0) redE[wp] = se;

        // ---- e-weighted out partials; e_i for row g+32i lives at lane
        //      (lane&16)|i of this warp — pure shfl, no smem, no sync ----
        float2 o01 = make_float2(0.f, 0.f), o23 = make_float2(0.f, 0.f);
#pragma unroll
        for (int i = 0; i < 16; ++i) {
            const float ei = __shfl_sync(0xffffffffu, e, (lane & 16) | i);
            const float2 ee = make_float2(ei, ei);
            o01 = fma2(make_float2(v[i].x, v[i].y), ee, o01);
            o23 = fma2(make_float2(v[i].z, v[i].w), ee, o23);
        }
        o01.x += __shfl_xor_sync(0xffffffffu, o01.x, 16);
        o01.y += __shfl_xor_sync(0xffffffffu, o01.y, 16);
        o23.x += __shfl_xor_sync(0xffffffffu, o23.x, 16);
        o23.y += __shfl_xor_sync(0xffffffffu, o23.y, 16);
        if (lane < 16)
            red4b[wp * 16 + lane] = make_float4(o01.x, o01.y, o23.x, o23.y);
        e_prev = e;
        // no trailing sync: red4b/redE consumed next iter after sync 0/1
    }

    // ---- epilogue: finalize last batch's wout and out ----
    __syncthreads();
    {
        const int lastb = b0 + (int)(nb - 1u) * NCTA;
        float tot = 0.0f;
#pragma unroll
        for (int k = 0; k < 16; ++k) tot += redE[k];
        const float sc = (tot > 0.0f) ? (1.0f / tot) : 0.0f;
        wout[lastb * SS + r] = e_prev * sc;
        if (t < 16) {
            float4 po = red4b[t];
#pragma unroll
            for (int k = 1; k < 16; ++k) {
                float4 o = red4b[t + 16 * k];
                po.x += o.x; po.y += o.y; po.z += o.z; po.w += o.w;
            }
            po.x *= sc; po.y *= sc; po.z *= sc; po.w *= sc;
            ((float4*)out)[lastb * 16 + t] = po;
        }
    }
}

extern "C" void kernel_launch(void* const* d_in, const int* in_sizes, int n_in,
                              void* d_out, int out_size) {
    const float* x    = (const float*)d_in[0];
    const int*   mask = (const int*)d_in[1];
    float* out  = (float*)d_out;                  // [B,1,D] -> B*D floats
    float* wout = out + (size_t)BB * DD;          // [B,S,1] -> B*S floats
    cudaFuncSetAttribute(attnsum_kernel,
                         cudaFuncAttributeMaxDynamicSharedMemorySize, SMEM_TOTAL);
    attnsum_kernel<<<NCTA, NT, SMEM_TOTAL>>>(x, mask, out, wout);
}

// round 14
// speedup vs baseline: 1.0844x; 1.0844x over previous
#include <cuda_runtime.h>
#include <cstdint>

#define BB 1024
#define SS 512
#define DD 64
#define NT 512
#define NCTA 148
#define HALF_BYTES 65536u
#define HALF_FLOATS 16384
#define SM_RED4A 196608              // 4 KB mean partials
#define SM_RED4B (SM_RED4A + 4096)   // 4 KB out partials (e-weighted)
#define SM_EXP   (SM_RED4B + 4096)   // 64 B per-warp exp sums
#define SM_MBAR  (SM_EXP + 64)       // 3 x 8B mbarriers
#define SMEM_TOTAL (SM_MBAR + 64)

__device__ __forceinline__ float2 add2(float2 a, float2 b) {
    float2 d;
    asm("{.reg .b64 ra,rb,rd;\n\t"
        "mov.b64 ra,{%2,%3}; mov.b64 rb,{%4,%5};\n\t"
        "add.rn.f32x2 rd,ra,rb; mov.b64 {%0,%1},rd;}"
        : "=f"(d.x), "=f"(d.y) : "f"(a.x), "f"(a.y), "f"(b.x), "f"(b.y));
    return d;
}
__device__ __forceinline__ float2 fma2(float2 a, float2 b, float2 c) {
    float2 d;
    asm("{.reg .b64 ra,rb,rc,rd;\n\t"
        "mov.b64 ra,{%2,%3}; mov.b64 rb,{%4,%5}; mov.b64 rc,{%6,%7};\n\t"
        "fma.rn.f32x2 rd,ra,rb,rc; mov.b64 {%0,%1},rd;}"
        : "=f"(d.x), "=f"(d.y)
        : "f"(a.x), "f"(a.y), "f"(b.x), "f"(b.y), "f"(c.x), "f"(c.y));
    return d;
}
__device__ __forceinline__ float2 mul2(float2 a, float2 b) {
    float2 d;
    asm("{.reg .b64 ra,rb,rd;\n\t"
        "mov.b64 ra,{%2,%3}; mov.b64 rb,{%4,%5};\n\t"
        "mul.rn.f32x2 rd,ra,rb; mov.b64 {%0,%1},rd;}"
        : "=f"(d.x), "=f"(d.y) : "f"(a.x), "f"(a.y), "f"(b.x), "f"(b.y));
    return d;
}

__device__ __forceinline__ void mbar_wait(uint32_t mbar, uint32_t parity) {
    uint32_t done;
    asm volatile(
        "{\n\t.reg .pred p;\n\t"
        "mbarrier.try_wait.parity.acquire.cta.shared::cta.b64 p, [%1], %2;\n\t"
        "selp.b32 %0, 1, 0, p;\n\t}"
        : "=r"(done) : "r"(mbar), "r"(parity) : "memory");
    while (!done) {
        asm volatile(
            "{\n\t.reg .pred p;\n\t"
            "mbarrier.try_wait.parity.acquire.cta.shared::cta.b64 p, [%1], %2, 0x989680;\n\t"
            "selp.b32 %0, 1, 0, p;\n\t}"
            : "=r"(done) : "r"(mbar), "r"(parity) : "memory");
    }
}

// Issue load of global half h into ring slot h%3. b(h) = b0 + (h>>1)*NCTA.
__device__ __forceinline__ void issue_half(uint32_t base_sa, uint32_t mbar_base_sa,
                                           const float* __restrict__ x, int b0, uint32_t h) {
    const uint32_t slot = h % 3u;
    const uint32_t mbar = mbar_base_sa + slot * 8u;
    const uint32_t dst  = base_sa + slot * HALF_BYTES;
    const int b = b0 + (int)(h >> 1) * NCTA;
    const char* src = (const char*)(x + (size_t)b * (SS * DD) + (h & 1u) * HALF_FLOATS);
    asm volatile("mbarrier.arrive.expect_tx.shared.b64 _, [%0], %1;"
                 :: "r"(mbar), "r"(HALF_BYTES) : "memory");
    asm volatile("cp.async.bulk.shared::cta.global.mbarrier::complete_tx::bytes [%0], [%1], %2, [%3];"
                 :: "r"(dst), "l"(src), "r"(HALF_BYTES), "r"(mbar) : "memory");
}

__global__ __launch_bounds__(NT, 1)
void attnsum_kernel(const float* __restrict__ x,
                    const int* __restrict__ mask,
                    float* __restrict__ out,    // [B, D]
                    float* __restrict__ wout)   // [B, S]
{
    extern __shared__ __align__(16) char smem[];
    float4* red4a = (float4*)(smem + SM_RED4A);
    float4* red4b = (float4*)(smem + SM_RED4B);
    float*  redE  = (float*)(smem + SM_EXP);

    const int t    = threadIdx.x;
    const int lane = t & 31;
    const int wp   = t >> 5;
    const int c    = t & 15;      // owned d-group: d = 4c..4c+3
    const int g    = t >> 4;      // row base: rows s = g + 32*i
    const int r    = g + 32 * c;  // row this thread owns after reduce-scatter

    const uint32_t base_sa = (uint32_t)__cvta_generic_to_shared(smem);
    const uint32_t mbar_sa = (uint32_t)__cvta_generic_to_shared(smem + SM_MBAR);

    if (t < 3)
        asm volatile("mbarrier.init.shared::cta.b64 [%0], 1;"
                     :: "r"(mbar_sa + t * 8u) : "memory");
    __syncthreads();

    const int b0 = blockIdx.x;
    uint32_t nb = 0;
    for (int b = b0; b < BB; b += NCTA) ++nb;
    const uint32_t totalH = 2u * nb;

    if (t == 0) {
        if (0 < totalH) issue_half(base_sa, mbar_sa, x, b0, 0);
        if (1 < totalH) issue_half(base_sa, mbar_sa, x, b0, 1);
        if (2 < totalH) issue_half(base_sa, mbar_sa, x, b0, 2);
    }

    float e_prev = 0.0f;   // this thread's unnormalized exp for row r, prev batch
    uint32_t h = 0;
    for (int b = b0; b < BB; b += NCTA, h += 2) {
        const int mk = mask[b * SS + r];   // gathered; early LDG

        // ---- consume two halves into registers; mean partials on half0 ----
        float4 v[16];
        float2 p01 = make_float2(0.f, 0.f), p23 = make_float2(0.f, 0.f);
        {
            const uint32_t s0 = h % 3u, pr0 = (h / 3u) & 1u;
            mbar_wait(mbar_sa + s0 * 8u, pr0);
            const float4* half0 = (const float4*)(smem + s0 * HALF_BYTES);
#pragma unroll
            for (int i = 0; i < 8; ++i) v[i] = half0[t + NT * i];
#pragma unroll
            for (int i = 0; i < 8; ++i) {
                p01 = add2(p01, make_float2(v[i].x, v[i].y));
                p23 = add2(p23, make_float2(v[i].z, v[i].w));
            }
            const uint32_t h1 = h + 1;
            const uint32_t s1 = h1 % 3u, pr1 = (h1 / 3u) & 1u;
            mbar_wait(mbar_sa + s1 * 8u, pr1);
            const float4* half1 = (const float4*)(smem + s1 * HALF_BYTES);
#pragma unroll
            for (int i = 0; i < 8; ++i) v[8 + i] = half1[t + NT * i];
        }
        __syncthreads();   // sync 0: tile slots free; prev redE/red4b stable
        if (t == 0) {
            if (h + 3 < totalH) issue_half(base_sa, mbar_sa, x, b0, h + 3);
            if (h + 4 < totalH) issue_half(base_sa, mbar_sa, x, b0, h + 4);
        }

        // ---- lazy normalize + store PREV batch's weights ----
        if (b != b0) {
            float tot = 0.0f;
#pragma unroll
            for (int k = 0; k < 16; ++k) tot += redE[k];
            const float sc = (tot > 0.0f) ? (1.0f / tot) : 0.0f;
            wout[(b - NCTA) * SS + r] = e_prev * sc;
        }

        // ---- mean partials (packed) ----
#pragma unroll
        for (int i = 8; i < 16; ++i) {
            p01 = add2(p01, make_float2(v[i].x, v[i].y));
            p23 = add2(p23, make_float2(v[i].z, v[i].w));
        }
        p01.x += __shfl_xor_sync(0xffffffffu, p01.x, 16);
        p01.y += __shfl_xor_sync(0xffffffffu, p01.y, 16);
        p23.x += __shfl_xor_sync(0xffffffffu, p23.x, 16);
        p23.y += __shfl_xor_sync(0xffffffffu, p23.y, 16);
        if (lane < 16)
            red4a[wp * 16 + lane] = make_float4(p01.x, p01.y, p23.x, p23.y);
        __syncthreads();   // sync 1

        // ---- t<16 window: finalize mean AND finalize+normalize prev out ----
        if (t < 16) {
            float4 m = red4a[t];
#pragma unroll
            for (int k = 1; k < 16; ++k) {
                float4 o = red4a[t + 16 * k];
                float2 a01 = add2(make_float2(m.x, m.y), make_float2(o.x, o.y));
                float2 a23 = add2(make_float2(m.z, m.w), make_float2(o.z, o.w));
                m = make_float4(a01.x, a01.y, a23.x, a23.y);
            }
            red4a[t] = m;
            if (b != b0) {
                float tot = 0.0f;
#pragma unroll
                for (int k = 0; k < 16; ++k) tot += redE[k];
                const float sc = (tot > 0.0f) ? (1.0f / tot) : 0.0f;
                float4 po = red4b[t];
#pragma unroll
                for (int k = 1; k < 16; ++k) {
                    float4 o = red4b[t + 16 * k];
                    float2 a01 = add2(make_float2(po.x, po.y), make_float2(o.x, o.y));
                    float2 a23 = add2(make_float2(po.z, po.w), make_float2(o.z, o.w));
                    po = make_float4(a01.x, a01.y, a23.x, a23.y);
                }
                po.x *= sc; po.y *= sc; po.z *= sc; po.w *= sc;
                ((float4*)out)[(b - NCTA) * 16 + t] = po;
            }
        }
        __syncthreads();   // sync 2
        float4 mean4 = red4a[c];
        const float invS = 1.0f / (float)SS;
        const float2 m01 = make_float2(mean4.x * invS, mean4.y * invS);
        const float2 m23 = make_float2(mean4.z * invS, mean4.w * invS);

        // ---- attn partials (packed dot4) ----
        float a[16];
#pragma unroll
        for (int i = 0; i < 16; ++i) {
            float2 p = mul2(make_float2(v[i].x, v[i].y), m01);
            p = fma2(make_float2(v[i].z, v[i].w), m23, p);
            a[i] = p.x + p.y;
        }
        // ---- log2 reduce-scatter over 16 c-lanes (15 shfls); lane c ends
        //      holding full attn for row r = g + 32*c ----
#pragma unroll
        for (int jj = 0; jj < 8; ++jj) {
            float send = (c & 8) ? a[jj] : a[jj + 8];
            float recv = __shfl_xor_sync(0xffffffffu, send, 8);
            a[jj] = ((c & 8) ? a[jj + 8] : a[jj]) + recv;
        }
#pragma unroll
        for (int jj = 0; jj < 4; ++jj) {
            float send = (c & 4) ? a[jj] : a[jj + 4];
            float recv = __shfl_xor_sync(0xffffffffu, send, 4);
            a[jj] = ((c & 4) ? a[jj + 4] : a[jj]) + recv;
        }
#pragma unroll
        for (int jj = 0; jj < 2; ++jj) {
            float send = (c & 2) ? a[jj] : a[jj + 2];
            float recv = __shfl_xor_sync(0xffffffffu, send, 2);
            a[jj] = ((c & 2) ? a[jj + 2] : a[jj]) + recv;
        }
        {
            float send = (c & 1) ? a[0] : a[1];
            float recv = __shfl_xor_sync(0xffffffffu, send, 1);
            a[0] = ((c & 1) ? a[1] : a[0]) + recv;
        }

        // ---- unnormalized exp; per-warp sum into redE ----
        const float e = mk ? __expf(a[0]) : 0.0f;
        float se = e;
        se += __shfl_xor_sync(0xffffffffu, se, 16);
        se += __shfl_xor_sync(0xffffffffu, se, 8);
        se += __shfl_xor_sync(0xffffffffu, se, 4);
        se += __shfl_xor_sync(0xffffffffu, se, 2);
        se += __shfl_xor_sync(0xffffffffu, se, 1);
        if (lane == 0) redE[wp] = se;

        // ---- e-weighted out partials; e_i for row g+32i lives at lane
        //      (lane&16)|i of this warp — pure shfl, no smem, no sync ----
        float2 o01 = make_float2(0.f, 0.f), o23 = make_float2(0.f, 0.f);
#pragma unroll
        for (int i = 0; i < 16; ++i) {
            const float ei = __shfl_sync(0xffffffffu, e, (lane & 16) | i);
            const float2 ee = make_float2(ei, ei);
            o01 = fma2(make_float2(v[i].x, v[i].y), ee, o01);
            o23 = fma2(make_float2(v[i].z, v[i].w), ee, o23);
        }
        o01.x += __shfl_xor_sync(0xffffffffu, o01.x, 16);
        o01.y += __shfl_xor_sync(0xffffffffu, o01.y, 16);
        o23.x += __shfl_xor_sync(0xffffffffu, o23.x, 16);
        o23.y += __shfl_xor_sync(0xffffffffu, o23.y, 16);
        if (lane < 16)
            red4b[wp * 16 + lane] = make_float4(o01.x, o01.y, o23.x, o23.y);
        e_prev = e;
        // no trailing sync: red4b/redE consumed next iter after sync 0/1
    }

    // ---- epilogue: finalize last batch's wout and out ----
    __syncthreads();
    {
        const int lastb = b0 + (int)(nb - 1u) * NCTA;
        float tot = 0.0f;
#pragma unroll
        for (int k = 0; k < 16; ++k) tot += redE[k];
        const float sc = (tot > 0.0f) ? (1.0f / tot) : 0.0f;
        wout[lastb * SS + r] = e_prev * sc;
        if (t < 16) {
            float4 po = red4b[t];
#pragma unroll
            for (int k = 1; k < 16; ++k) {
                float4 o = red4b[t + 16 * k];
                po.x += o.x; po.y += o.y; po.z += o.z; po.w += o.w;
            }
            po.x *= sc; po.y *= sc; po.z *= sc; po.w *= sc;
            ((float4*)out)[lastb * 16 + t] = po;
        }
    }
}

extern "C" void kernel_launch(void* const* d_in, const int* in_sizes, int n_in,
                              void* d_out, int out_size) {
    const float* x    = (const float*)d_in[0];
    const int*   mask = (const int*)d_in[1];
    float* out  = (float*)d_out;                  // [B,1,D] -> B*D floats
    float* wout = out + (size_t)BB * DD;          // [B,S,1] -> B*S floats
    cudaFuncSetAttribute(attnsum_kernel,
                         cudaFuncAttributeMaxDynamicSharedMemorySize, SMEM_TOTAL);
    attnsum_kernel<<<NCTA, NT, SMEM_TOTAL>>>(x, mask, out, wout);
}